// round 1
// baseline (speedup 1.0000x reference)
#include <cuda_runtime.h>
#include <cuda_bf16.h>

#define HID   64
#define NFLD  2
#define NHH   32
#define NMF   8
#define NTS   4
#define NLAY  9          // hidden (relu,linear) layers in edge MLP
#define MAXN  10016

// ---------------- scratch (device globals; no allocation allowed) -----------
__device__ float g_Ptop[MAXN * HID];
__device__ float g_Pbot[MAXN * HID];
__device__ float g_acc [MAXN * HID];
__device__ float g_meshh[MAXN * NHH];
__device__ float g_henc[MAXN * HID];
__device__ float g_Fprev[MAXN * NFLD];

// ---------------- per-node projection for mesh-descriptor pass --------------
// Ptop = X @ W0[0:8,:], Pbot = X @ W0[8:16,:]; also zero the scatter acc.
__global__ void proj_md_kernel(const float* __restrict__ X,
                               const float* __restrict__ W0,
                               float* __restrict__ Ptop, float* __restrict__ Pbot,
                               float* __restrict__ acc, int Nn)
{
    int idx = blockIdx.x * blockDim.x + threadIdx.x;
    if (idx >= Nn * HID) return;
    int n = idx >> 6, j = idx & 63;
    float st = 0.f, sb = 0.f;
#pragma unroll
    for (int k = 0; k < NMF; k++) {
        float x = X[n * NMF + k];
        st = fmaf(x, W0[k * HID + j], st);
        sb = fmaf(x, W0[(NMF + k) * HID + j], sb);
    }
    Ptop[idx] = st;
    Pbot[idx] = sb;
    acc[idx]  = 0.f;
}

// ---------------- node encoder for derivative solver ------------------------
// F_temp = [mesh_h(32), F_prev(2), F_b(1)];  h = relu(F_temp @ W + b)
__global__ void enc_ds_kernel(const float* __restrict__ meshh,
                              const float* __restrict__ Fprev,
                              const float* __restrict__ Fb, int t,
                              const float* __restrict__ W,
                              const float* __restrict__ b,
                              float* __restrict__ henc, int Nn)
{
    int idx = blockIdx.x * blockDim.x + threadIdx.x;
    if (idx >= Nn * HID) return;
    int n = idx >> 6, j = idx & 63;
    float s = b[j];
#pragma unroll
    for (int k = 0; k < NHH; k++)
        s = fmaf(meshh[n * NHH + k], W[k * HID + j], s);
    s = fmaf(Fprev[n * NFLD + 0], W[(NHH + 0) * HID + j], s);
    s = fmaf(Fprev[n * NFLD + 1], W[(NHH + 1) * HID + j], s);
    s = fmaf(Fb[n * NTS + t],     W[(NHH + 2) * HID + j], s);
    henc[idx] = fmaxf(s, 0.f);
}

// ---------------- per-node projection for ds pass ---------------------------
__global__ void proj_ds_kernel(const float* __restrict__ Xh,
                               const float* __restrict__ W0,
                               float* __restrict__ Ptop, float* __restrict__ Pbot,
                               float* __restrict__ acc, int Nn)
{
    int idx = blockIdx.x * blockDim.x + threadIdx.x;
    if (idx >= Nn * HID) return;
    int n = idx >> 6, j = idx & 63;
    float st = 0.f, sb = 0.f;
#pragma unroll 8
    for (int k = 0; k < HID; k++) {
        float x = Xh[n * HID + k];
        st = fmaf(x, W0[k * HID + j], st);
        sb = fmaf(x, W0[(HID + k) * HID + j], sb);
    }
    Ptop[idx] = st;
    Pbot[idx] = sb;
    acc[idx]  = 0.f;
}

// ---------------- fused edge MLP + scatter -----------------------------------
// Tile: 128 edges x 64 hidden.  h0 = Ptop[dst] + Pbot[src] + b0, then
// 9 x { relu, 64x64 linear } in SMEM; epilogue atomic segment-sum by src.
// dyn smem: A ping/pong 2*64*128 floats + W stage 64*64 floats = 81920 B.
__global__ void __launch_bounds__(256, 2)
edge_mlp_kernel(const float* __restrict__ Ptop, const float* __restrict__ Pbot,
                const float* __restrict__ b0,
                const float* __restrict__ Wh,  // (9,64,64)
                const float* __restrict__ Bh,  // (9,64)
                const int* __restrict__ src, const int* __restrict__ dst,
                float* __restrict__ acc, int E)
{
    extern __shared__ float smem[];
    float* A0 = smem;                 // [64][128]
    float* A1 = smem + 64 * 128;      // [64][128]
    float* Ws = smem + 2 * 64 * 128;  // [64][64]

    const int tid = threadIdx.x;
    const int te  = tid & 31;         // edge-quad index (4 edges each)
    const int tj  = tid >> 5;         // column-octet index (8 cols each)
    const int e0  = blockIdx.x * 128;

    // ---- prologue: gather h0 into A0[k][e] (conflict-free STS mapping) ----
    for (int i = tid; i < 128 * 16; i += 256) {
        int kq = i >> 7;            // float4 group 0..15  (same within a warp)
        int e  = i & 127;           // edge              (consecutive lanes)
        int ge = e0 + e;
        float4 vt = make_float4(0.f, 0.f, 0.f, 0.f);
        float4 vb = make_float4(0.f, 0.f, 0.f, 0.f);
        if (ge < E) {
            int d = dst[ge], s = src[ge];
            vt = *(const float4*)(Ptop + d * HID + kq * 4);
            vb = *(const float4*)(Pbot + s * HID + kq * 4);
        }
        float4 bb = *(const float4*)(b0 + kq * 4);
        int k = kq * 4;
        A0[(k + 0) * 128 + e] = vt.x + vb.x + bb.x;
        A0[(k + 1) * 128 + e] = vt.y + vb.y + bb.y;
        A0[(k + 2) * 128 + e] = vt.z + vb.z + bb.z;
        A0[(k + 3) * 128 + e] = vt.w + vb.w + bb.w;
    }
    __syncthreads();

    float* Acur = A0;
    float* Anxt = A1;

    for (int l = 0; l < NLAY; l++) {
        // stage this layer's weights
        const float4* Wg = (const float4*)(Wh + l * HID * HID);
        for (int i = tid; i < HID * HID / 4; i += 256)
            ((float4*)Ws)[i] = Wg[i];
        __syncthreads();

        float accr[4][8];
#pragma unroll
        for (int jj = 0; jj < 8; jj++) {
            float bj = Bh[l * HID + tj * 8 + jj];
#pragma unroll
            for (int q = 0; q < 4; q++) accr[q][jj] = bj;
        }

#pragma unroll 8
        for (int k = 0; k < HID; k++) {
            float4 a4 = *(const float4*)(Acur + (k << 7) + (te << 2));
            float av[4];
            av[0] = fmaxf(a4.x, 0.f); av[1] = fmaxf(a4.y, 0.f);
            av[2] = fmaxf(a4.z, 0.f); av[3] = fmaxf(a4.w, 0.f);
            float4 w0 = *(const float4*)(Ws + (k << 6) + (tj << 3));
            float4 w1 = *(const float4*)(Ws + (k << 6) + (tj << 3) + 4);
            float wv[8] = {w0.x, w0.y, w0.z, w0.w, w1.x, w1.y, w1.z, w1.w};
#pragma unroll
            for (int q = 0; q < 4; q++)
#pragma unroll
                for (int jj = 0; jj < 8; jj++)
                    accr[q][jj] = fmaf(av[q], wv[jj], accr[q][jj]);
        }

        // write next activations [j][e] (no sync needed before: disjoint buffer)
#pragma unroll
        for (int jj = 0; jj < 8; jj++) {
            float4 v = make_float4(accr[0][jj], accr[1][jj], accr[2][jj], accr[3][jj]);
            *(float4*)(Anxt + ((tj * 8 + jj) << 7) + (te << 2)) = v;
        }
        float* tmp = Acur; Acur = Anxt; Anxt = tmp;
        __syncthreads();
    }

    // ---- epilogue: segment-sum scatter by src ----
    int e    = tid >> 1;
    int half = tid & 1;
    int ge   = e0 + e;
    if (ge < E) {
        int node = src[ge];
        float* ap = acc + node * HID + half * 32;
#pragma unroll
        for (int kk = 0; kk < 32; kk++)
            atomicAdd(ap + kk, Acur[((half * 32 + kk) << 7) + e]);
    }
}

// ---------------- node decoder (mesh descriptor) -----------------------------
__global__ void dec_md_kernel(const float* __restrict__ acc,
                              const float* __restrict__ dw1, const float* __restrict__ db1,
                              const float* __restrict__ dw2, const float* __restrict__ db2,
                              float* __restrict__ meshh, int Nn)
{
    __shared__ float t1[4][64];
    int tid = threadIdx.x;
    int q = tid >> 6, j = tid & 63;
    int n = blockIdx.x * 4 + q;
    float s = db1[j];
    if (n < Nn) {
#pragma unroll 8
        for (int k = 0; k < HID; k++)
            s = fmaf(acc[n * HID + k], dw1[k * HID + j], s);
    }
    t1[q][j] = fmaxf(s, 0.f);
    __syncthreads();
    if (tid < 128) {
        int q2 = tid >> 5, j2 = tid & 31;
        int n2 = blockIdx.x * 4 + q2;
        if (n2 < Nn) {
            float o = db2[j2];
#pragma unroll 8
            for (int k = 0; k < HID; k++)
                o = fmaf(t1[q2][k], dw2[k * NHH + j2], o);
            meshh[n2 * NHH + j2] = o;
        }
    }
}

// ---------------- node decoder (ds) + Euler step + output --------------------
__global__ void dec_ds_kernel(const float* __restrict__ acc,
                              const float* __restrict__ dw1, const float* __restrict__ db1,
                              const float* __restrict__ dw2, const float* __restrict__ db2,
                              const float* __restrict__ Fprev_in,
                              const float* __restrict__ dtp,
                              float* __restrict__ Fprev_out,
                              float* __restrict__ outF, float* __restrict__ outFd,
                              int step, int nsteps, int Nn)
{
    __shared__ float t1[4][64];
    int tid = threadIdx.x;
    int q = tid >> 6, j = tid & 63;
    int n = blockIdx.x * 4 + q;
    float s = db1[j];
    if (n < Nn) {
#pragma unroll 8
        for (int k = 0; k < HID; k++)
            s = fmaf(acc[n * HID + k], dw1[k * HID + j], s);
    }
    t1[q][j] = fmaxf(s, 0.f);
    __syncthreads();
    if (tid < 8) {
        int q2 = tid >> 1, f = tid & 1;
        int n2 = blockIdx.x * 4 + q2;
        if (n2 < Nn) {
            float o = db2[f];
#pragma unroll 8
            for (int k = 0; k < HID; k++)
                o = fmaf(t1[q2][k], dw2[k * NFLD + f], o);
            float fp = Fprev_in[n2 * NFLD + f];
            float fc = fmaf(dtp[0], o, fp);
            outF [(n2 * nsteps + step) * NFLD + f] = fc;
            outFd[(n2 * nsteps + step) * NFLD + f] = o;
            Fprev_out[n2 * NFLD + f] = fc;
        }
    }
}

// ---------------- launch ------------------------------------------------------
extern "C" void kernel_launch(void* const* d_in, const int* in_sizes, int n_in,
                              void* d_out, int out_size)
{
    const float* F_initial     = (const float*)d_in[0];
    const float* mesh_features = (const float*)d_in[1];
    const int*   edge_index    = (const int*)  d_in[2];
    const float* F_boundary    = (const float*)d_in[3];
    const float* dtp           = (const float*)d_in[4];
    const float* md_w0  = (const float*)d_in[5];
    const float* md_b0  = (const float*)d_in[6];
    const float* md_wh  = (const float*)d_in[7];
    const float* md_bh  = (const float*)d_in[8];
    const float* md_dw1 = (const float*)d_in[9];
    const float* md_db1 = (const float*)d_in[10];
    const float* md_dw2 = (const float*)d_in[11];
    const float* md_db2 = (const float*)d_in[12];
    const float* ds_encw = (const float*)d_in[13];
    const float* ds_encb = (const float*)d_in[14];
    const float* ds_w0  = (const float*)d_in[15];
    const float* ds_b0  = (const float*)d_in[16];
    const float* ds_wh  = (const float*)d_in[17];
    const float* ds_bh  = (const float*)d_in[18];
    const float* ds_dw1 = (const float*)d_in[19];
    const float* ds_db1 = (const float*)d_in[20];
    const float* ds_dw2 = (const float*)d_in[21];
    const float* ds_db2 = (const float*)d_in[22];

    int Nn = in_sizes[0] / NFLD;
    int E  = in_sizes[2] / 2;

    float *Ptop, *Pbot, *acc, *meshh, *henc, *Fprev;
    cudaGetSymbolAddress((void**)&Ptop,  g_Ptop);
    cudaGetSymbolAddress((void**)&Pbot,  g_Pbot);
    cudaGetSymbolAddress((void**)&acc,   g_acc);
    cudaGetSymbolAddress((void**)&meshh, g_meshh);
    cudaGetSymbolAddress((void**)&henc,  g_henc);
    cudaGetSymbolAddress((void**)&Fprev, g_Fprev);

    const size_t SMEM = (size_t)(2 * 64 * 128 + 64 * 64) * sizeof(float);  // 81920
    cudaFuncSetAttribute(edge_mlp_kernel,
                         cudaFuncAttributeMaxDynamicSharedMemorySize, (int)SMEM);

    const int* srcp = edge_index;
    const int* dstp = edge_index + E;

    int nb_node = (Nn * HID + 255) / 256;
    int nb_edge = (E + 127) / 128;
    int nb_dec  = (Nn + 3) / 4;
    int nsteps  = NTS - 1;

    float* outF  = (float*)d_out;
    float* outFd = outF + (size_t)out_size / 2;

    // ---- mesh descriptor pass ----
    proj_md_kernel<<<nb_node, 256>>>(mesh_features, md_w0, Ptop, Pbot, acc, Nn);
    edge_mlp_kernel<<<nb_edge, 256, SMEM>>>(Ptop, Pbot, md_b0, md_wh, md_bh,
                                            srcp, dstp, acc, E);
    dec_md_kernel<<<nb_dec, 256>>>(acc, md_dw1, md_db1, md_dw2, md_db2, meshh, Nn);

    // ---- timesteps ----
    for (int t = 1; t < NTS; t++) {
        const float* fprev_in = (t == 1) ? F_initial : (const float*)Fprev;
        enc_ds_kernel<<<nb_node, 256>>>(meshh, fprev_in, F_boundary, t,
                                        ds_encw, ds_encb, henc, Nn);
        proj_ds_kernel<<<nb_node, 256>>>(henc, ds_w0, Ptop, Pbot, acc, Nn);
        edge_mlp_kernel<<<nb_edge, 256, SMEM>>>(Ptop, Pbot, ds_b0, ds_wh, ds_bh,
                                                srcp, dstp, acc, E);
        dec_ds_kernel<<<nb_dec, 256>>>(acc, ds_dw1, ds_db1, ds_dw2, ds_db2,
                                       fprev_in, dtp, Fprev, outF, outFd,
                                       t - 1, nsteps, Nn);
    }
}

// round 2
// speedup vs baseline: 1.2316x; 1.2316x over previous
#include <cuda_runtime.h>
#include <cuda_bf16.h>

#define HID   64
#define NFLD  2
#define NHH   32
#define NMF   8
#define NTS   4
#define NLAY  9          // hidden (relu,linear) layers in edge MLP
#define MAXN  10016

// ---------------- scratch (device globals; no allocation allowed) -----------
__device__ float g_Ptop[MAXN * HID];
__device__ float g_Pbot[MAXN * HID];
__device__ float g_acc [MAXN * HID];
__device__ float g_meshh[MAXN * NHH];
__device__ float g_henc[MAXN * HID];
__device__ float g_Fprev[MAXN * NFLD];

// ---------------- packed fp32 helpers (FFMA2 path) ---------------------------
__device__ __forceinline__ unsigned long long pack2(float x, float y) {
    unsigned long long r;
    asm("mov.b64 %0, {%1, %2};" : "=l"(r) : "f"(x), "f"(y));
    return r;
}
__device__ __forceinline__ unsigned long long dup2(float x) {
    unsigned long long r;
    asm("mov.b64 %0, {%1, %1};" : "=l"(r) : "f"(x));
    return r;
}
__device__ __forceinline__ float2 unpack2(unsigned long long v) {
    float2 r;
    asm("mov.b64 {%0, %1}, %2;" : "=f"(r.x), "=f"(r.y) : "l"(v));
    return r;
}
__device__ __forceinline__ void ffma2(unsigned long long& d,
                                      unsigned long long a, unsigned long long b) {
    asm("fma.rn.f32x2 %0, %1, %2, %0;" : "+l"(d) : "l"(a), "l"(b));
}

// ---------------- per-node projection for mesh-descriptor pass --------------
__global__ void proj_md_kernel(const float* __restrict__ X,
                               const float* __restrict__ W0,
                               float* __restrict__ Ptop, float* __restrict__ Pbot,
                               float* __restrict__ acc, int Nn)
{
    int idx = blockIdx.x * blockDim.x + threadIdx.x;
    if (idx >= Nn * HID) return;
    int n = idx >> 6, j = idx & 63;
    float st = 0.f, sb = 0.f;
#pragma unroll
    for (int k = 0; k < NMF; k++) {
        float x = X[n * NMF + k];
        st = fmaf(x, W0[k * HID + j], st);
        sb = fmaf(x, W0[(NMF + k) * HID + j], sb);
    }
    Ptop[idx] = st;
    Pbot[idx] = sb;
    acc[idx]  = 0.f;
}

// ---------------- node encoder for derivative solver ------------------------
__global__ void enc_ds_kernel(const float* __restrict__ meshh,
                              const float* __restrict__ Fprev,
                              const float* __restrict__ Fb, int t,
                              const float* __restrict__ W,
                              const float* __restrict__ b,
                              float* __restrict__ henc, int Nn)
{
    int idx = blockIdx.x * blockDim.x + threadIdx.x;
    if (idx >= Nn * HID) return;
    int n = idx >> 6, j = idx & 63;
    float s = b[j];
#pragma unroll
    for (int k = 0; k < NHH; k++)
        s = fmaf(meshh[n * NHH + k], W[k * HID + j], s);
    s = fmaf(Fprev[n * NFLD + 0], W[(NHH + 0) * HID + j], s);
    s = fmaf(Fprev[n * NFLD + 1], W[(NHH + 1) * HID + j], s);
    s = fmaf(Fb[n * NTS + t],     W[(NHH + 2) * HID + j], s);
    henc[idx] = fmaxf(s, 0.f);
}

// ---------------- per-node projection for ds pass ---------------------------
__global__ void proj_ds_kernel(const float* __restrict__ Xh,
                               const float* __restrict__ W0,
                               float* __restrict__ Ptop, float* __restrict__ Pbot,
                               float* __restrict__ acc, int Nn)
{
    int idx = blockIdx.x * blockDim.x + threadIdx.x;
    if (idx >= Nn * HID) return;
    int n = idx >> 6, j = idx & 63;
    float st = 0.f, sb = 0.f;
#pragma unroll 8
    for (int k = 0; k < HID; k++) {
        float x = Xh[n * HID + k];
        st = fmaf(x, W0[k * HID + j], st);
        sb = fmaf(x, W0[(HID + k) * HID + j], sb);
    }
    Ptop[idx] = st;
    Pbot[idx] = sb;
    acc[idx]  = 0.f;
}

// ---------------- fused edge MLP + scatter -----------------------------------
// Tile: 128 edges x 64 hidden.  A0 = relu(Ptop[dst]+Pbot[src]+b0), then
// 9 x { 64x64 linear (FFMA2), relu at store (except last) }; epilogue atomic
// segment-sum by src.  dyn smem: A ping/pong 2*64*128 + W ping/pong 2*64*64
// floats = 98304 B.  One __syncthreads per layer (double-buffered weights).
__global__ void __launch_bounds__(256, 2)
edge_mlp_kernel(const float* __restrict__ Ptop, const float* __restrict__ Pbot,
                const float* __restrict__ b0,
                const float* __restrict__ Wh,  // (9,64,64)
                const float* __restrict__ Bh,  // (9,64)
                const int* __restrict__ src, const int* __restrict__ dst,
                float* __restrict__ acc, int E)
{
    extern __shared__ float smem[];
    float* A0  = smem;                       // [64][128]
    float* A1  = smem + 64 * 128;            // [64][128]
    float* Ws0 = smem + 2 * 64 * 128;        // [64][64]
    float* Ws1 = Ws0 + 64 * 64;              // [64][64]

    const int tid = threadIdx.x;
    const int te  = tid & 31;         // edge-quad index (4 edges each)
    const int tj  = tid >> 5;         // column-octet index (8 cols each)
    const int e0  = blockIdx.x * 128;

    // ---- prologue: gather h0 = relu(Ptop[dst]+Pbot[src]+b0) into A0[k][e] ----
    for (int i = tid; i < 128 * 16; i += 256) {
        int kq = i >> 7;            // float4 group 0..15 (same within a warp)
        int e  = i & 127;           // edge (consecutive lanes)
        int ge = e0 + e;
        float4 vt = make_float4(0.f, 0.f, 0.f, 0.f);
        float4 vb = make_float4(0.f, 0.f, 0.f, 0.f);
        if (ge < E) {
            int d = dst[ge], s = src[ge];
            vt = *(const float4*)(Ptop + d * HID + kq * 4);
            vb = *(const float4*)(Pbot + s * HID + kq * 4);
        }
        float4 bb = *(const float4*)(b0 + kq * 4);
        int k = kq * 4;
        A0[(k + 0) * 128 + e] = fmaxf(vt.x + vb.x + bb.x, 0.f);
        A0[(k + 1) * 128 + e] = fmaxf(vt.y + vb.y + bb.y, 0.f);
        A0[(k + 2) * 128 + e] = fmaxf(vt.z + vb.z + bb.z, 0.f);
        A0[(k + 3) * 128 + e] = fmaxf(vt.w + vb.w + bb.w, 0.f);
    }

    // stage layer-0 weights into Ws0
    {
        const float4* Wg = (const float4*)Wh;
        for (int i = tid; i < HID * HID / 4; i += 256)
            ((float4*)Ws0)[i] = Wg[i];
    }

    float* Acur = A0;
    float* Anxt = A1;
    float* Wcur = Ws0;
    float* Wnxt = Ws1;

    for (int l = 0; l < NLAY; l++) {
        __syncthreads();   // A(cur) + W(cur) ready; prior reads of W(nxt) done

        // prefetch next layer's weights into the other buffer
        if (l + 1 < NLAY) {
            const float4* Wg = (const float4*)(Wh + (l + 1) * HID * HID);
            for (int i = tid; i < HID * HID / 4; i += 256)
                ((float4*)Wnxt)[i] = Wg[i];
        }

        // bias init: packed column pairs, replicated over the 4 edges
        unsigned long long acc2[4][4];
#pragma unroll
        for (int jp = 0; jp < 4; jp++) {
            float2 b2 = *(const float2*)(Bh + l * HID + (tj << 3) + jp * 2);
            unsigned long long bp = pack2(b2.x, b2.y);
#pragma unroll
            for (int q = 0; q < 4; q++) acc2[q][jp] = bp;
        }

#pragma unroll 8
        for (int k = 0; k < HID; k++) {
            float4 a4 = *(const float4*)(Acur + (k << 7) + (te << 2));
            unsigned long long ap[4];
            ap[0] = dup2(a4.x); ap[1] = dup2(a4.y);
            ap[2] = dup2(a4.z); ap[3] = dup2(a4.w);
            ulonglong2 w01 = *(const ulonglong2*)(Wcur + (k << 6) + (tj << 3));
            ulonglong2 w23 = *(const ulonglong2*)(Wcur + (k << 6) + (tj << 3) + 4);
            unsigned long long wp[4] = {w01.x, w01.y, w23.x, w23.y};
#pragma unroll
            for (int q = 0; q < 4; q++)
#pragma unroll
                for (int jp = 0; jp < 4; jp++)
                    ffma2(acc2[q][jp], ap[q], wp[jp]);
        }

        // write next activations [j][e]; relu here except for the last layer
        const bool dorelu = (l != NLAY - 1);
#pragma unroll
        for (int jp = 0; jp < 4; jp++) {
            float2 v0 = unpack2(acc2[0][jp]);
            float2 v1 = unpack2(acc2[1][jp]);
            float2 v2 = unpack2(acc2[2][jp]);
            float2 v3 = unpack2(acc2[3][jp]);
            float4 c0 = make_float4(v0.x, v1.x, v2.x, v3.x);
            float4 c1 = make_float4(v0.y, v1.y, v2.y, v3.y);
            if (dorelu) {
                c0.x = fmaxf(c0.x, 0.f); c0.y = fmaxf(c0.y, 0.f);
                c0.z = fmaxf(c0.z, 0.f); c0.w = fmaxf(c0.w, 0.f);
                c1.x = fmaxf(c1.x, 0.f); c1.y = fmaxf(c1.y, 0.f);
                c1.z = fmaxf(c1.z, 0.f); c1.w = fmaxf(c1.w, 0.f);
            }
            int j0 = (tj << 3) + jp * 2;
            *(float4*)(Anxt + ((j0 + 0) << 7) + (te << 2)) = c0;
            *(float4*)(Anxt + ((j0 + 1) << 7) + (te << 2)) = c1;
        }

        float* t;
        t = Acur; Acur = Anxt; Anxt = t;
        t = Wcur; Wcur = Wnxt; Wnxt = t;
    }
    __syncthreads();

    // ---- epilogue: segment-sum scatter by src ----
    int e    = tid >> 1;
    int half = tid & 1;
    int ge   = e0 + e;
    if (ge < E) {
        int node = src[ge];
        float* ap = acc + node * HID + half * 32;
#pragma unroll
        for (int kk = 0; kk < 32; kk++)
            atomicAdd(ap + kk, Acur[((half * 32 + kk) << 7) + e]);
    }
}

// ---------------- node decoder (mesh descriptor) -----------------------------
__global__ void dec_md_kernel(const float* __restrict__ acc,
                              const float* __restrict__ dw1, const float* __restrict__ db1,
                              const float* __restrict__ dw2, const float* __restrict__ db2,
                              float* __restrict__ meshh, int Nn)
{
    __shared__ float t1[4][64];
    int tid = threadIdx.x;
    int q = tid >> 6, j = tid & 63;
    int n = blockIdx.x * 4 + q;
    float s = db1[j];
    if (n < Nn) {
#pragma unroll 8
        for (int k = 0; k < HID; k++)
            s = fmaf(acc[n * HID + k], dw1[k * HID + j], s);
    }
    t1[q][j] = fmaxf(s, 0.f);
    __syncthreads();
    if (tid < 128) {
        int q2 = tid >> 5, j2 = tid & 31;
        int n2 = blockIdx.x * 4 + q2;
        if (n2 < Nn) {
            float o = db2[j2];
#pragma unroll 8
            for (int k = 0; k < HID; k++)
                o = fmaf(t1[q2][k], dw2[k * NHH + j2], o);
            meshh[n2 * NHH + j2] = o;
        }
    }
}

// ---------------- node decoder (ds) + Euler step + output --------------------
__global__ void dec_ds_kernel(const float* __restrict__ acc,
                              const float* __restrict__ dw1, const float* __restrict__ db1,
                              const float* __restrict__ dw2, const float* __restrict__ db2,
                              const float* __restrict__ Fprev_in,
                              const float* __restrict__ dtp,
                              float* __restrict__ Fprev_out,
                              float* __restrict__ outF, float* __restrict__ outFd,
                              int step, int nsteps, int Nn)
{
    __shared__ float t1[4][64];
    int tid = threadIdx.x;
    int q = tid >> 6, j = tid & 63;
    int n = blockIdx.x * 4 + q;
    float s = db1[j];
    if (n < Nn) {
#pragma unroll 8
        for (int k = 0; k < HID; k++)
            s = fmaf(acc[n * HID + k], dw1[k * HID + j], s);
    }
    t1[q][j] = fmaxf(s, 0.f);
    __syncthreads();
    if (tid < 8) {
        int q2 = tid >> 1, f = tid & 1;
        int n2 = blockIdx.x * 4 + q2;
        if (n2 < Nn) {
            float o = db2[f];
#pragma unroll 8
            for (int k = 0; k < HID; k++)
                o = fmaf(t1[q2][k], dw2[k * NFLD + f], o);
            float fp = Fprev_in[n2 * NFLD + f];
            float fc = fmaf(dtp[0], o, fp);
            outF [(n2 * nsteps + step) * NFLD + f] = fc;
            outFd[(n2 * nsteps + step) * NFLD + f] = o;
            Fprev_out[n2 * NFLD + f] = fc;
        }
    }
}

// ---------------- launch ------------------------------------------------------
extern "C" void kernel_launch(void* const* d_in, const int* in_sizes, int n_in,
                              void* d_out, int out_size)
{
    const float* F_initial     = (const float*)d_in[0];
    const float* mesh_features = (const float*)d_in[1];
    const int*   edge_index    = (const int*)  d_in[2];
    const float* F_boundary    = (const float*)d_in[3];
    const float* dtp           = (const float*)d_in[4];
    const float* md_w0  = (const float*)d_in[5];
    const float* md_b0  = (const float*)d_in[6];
    const float* md_wh  = (const float*)d_in[7];
    const float* md_bh  = (const float*)d_in[8];
    const float* md_dw1 = (const float*)d_in[9];
    const float* md_db1 = (const float*)d_in[10];
    const float* md_dw2 = (const float*)d_in[11];
    const float* md_db2 = (const float*)d_in[12];
    const float* ds_encw = (const float*)d_in[13];
    const float* ds_encb = (const float*)d_in[14];
    const float* ds_w0  = (const float*)d_in[15];
    const float* ds_b0  = (const float*)d_in[16];
    const float* ds_wh  = (const float*)d_in[17];
    const float* ds_bh  = (const float*)d_in[18];
    const float* ds_dw1 = (const float*)d_in[19];
    const float* ds_db1 = (const float*)d_in[20];
    const float* ds_dw2 = (const float*)d_in[21];
    const float* ds_db2 = (const float*)d_in[22];

    int Nn = in_sizes[0] / NFLD;
    int E  = in_sizes[2] / 2;

    float *Ptop, *Pbot, *acc, *meshh, *henc, *Fprev;
    cudaGetSymbolAddress((void**)&Ptop,  g_Ptop);
    cudaGetSymbolAddress((void**)&Pbot,  g_Pbot);
    cudaGetSymbolAddress((void**)&acc,   g_acc);
    cudaGetSymbolAddress((void**)&meshh, g_meshh);
    cudaGetSymbolAddress((void**)&henc,  g_henc);
    cudaGetSymbolAddress((void**)&Fprev, g_Fprev);

    const size_t SMEM = (size_t)(2 * 64 * 128 + 2 * 64 * 64) * sizeof(float);  // 98304
    cudaFuncSetAttribute(edge_mlp_kernel,
                         cudaFuncAttributeMaxDynamicSharedMemorySize, (int)SMEM);

    const int* srcp = edge_index;
    const int* dstp = edge_index + E;

    int nb_node = (Nn * HID + 255) / 256;
    int nb_edge = (E + 127) / 128;
    int nb_dec  = (Nn + 3) / 4;
    int nsteps  = NTS - 1;

    float* outF  = (float*)d_out;
    float* outFd = outF + (size_t)out_size / 2;

    // ---- mesh descriptor pass ----
    proj_md_kernel<<<nb_node, 256>>>(mesh_features, md_w0, Ptop, Pbot, acc, Nn);
    edge_mlp_kernel<<<nb_edge, 256, SMEM>>>(Ptop, Pbot, md_b0, md_wh, md_bh,
                                            srcp, dstp, acc, E);
    dec_md_kernel<<<nb_dec, 256>>>(acc, md_dw1, md_db1, md_dw2, md_db2, meshh, Nn);

    // ---- timesteps ----
    for (int t = 1; t < NTS; t++) {
        const float* fprev_in = (t == 1) ? F_initial : (const float*)Fprev;
        enc_ds_kernel<<<nb_node, 256>>>(meshh, fprev_in, F_boundary, t,
                                        ds_encw, ds_encb, henc, Nn);
        proj_ds_kernel<<<nb_node, 256>>>(henc, ds_w0, Ptop, Pbot, acc, Nn);
        edge_mlp_kernel<<<nb_edge, 256, SMEM>>>(Ptop, Pbot, ds_b0, ds_wh, ds_bh,
                                                srcp, dstp, acc, E);
        dec_ds_kernel<<<nb_dec, 256>>>(acc, ds_dw1, ds_db1, ds_dw2, ds_db2,
                                       fprev_in, dtp, Fprev, outF, outFd,
                                       t - 1, nsteps, Nn);
    }
}